// round 1
// baseline (speedup 1.0000x reference)
#include <cuda_runtime.h>

// GraphSAGE 2-layer inference, fused.
// Sizes fixed by the problem:
#define N0V   8192
#define N1V   100000
#define N2V   300000
#define KNBR  32
#define DD    64

// Scratch (device globals — no allocation allowed in kernel_launch).
__device__ float g_v2[(size_t)N2V * DD];   // 76.8 MB  (fits L2 once resident)
__device__ float g_h1[(size_t)N1V * DD];   // 25.6 MB

// ---------------------------------------------------------------------------
// Kernel A: materialize v2 = feats[node_ids2]   (index composition so the
// hop-1 gather target is 76.8MB instead of the 128MB feature table)
// ---------------------------------------------------------------------------
__global__ void gather_v2_kernel(const float* __restrict__ feats,
                                 const int*   __restrict__ node_ids2)
{
    int t = blockIdx.x * blockDim.x + threadIdx.x;
    const int total = N2V * (DD / 4);          // float4 granularity
    if (t >= total) return;
    int row = t >> 4;                          // DD/4 = 16 float4 per row
    int c   = t & 15;
    int src = __ldg(node_ids2 + row);
    float4 v = __ldg((const float4*)(feats + (size_t)src * DD) + c);
    ((float4*)(g_v2 + (size_t)row * DD))[c] = v;
}

// ---------------------------------------------------------------------------
// Kernel B/C: per row — mean over KNBR neighbor rows, then x@W + b, ReLU.
// One warp per output row. W (64x64) and bias staged in shared memory.
// Neighbor indices: each lane holds one of the 32 indices; broadcast by
// __shfl_sync so the fully-unrolled gather loop issues 32 independent
// coalesced 256B row loads (high MLP, hides L2 latency).
// ---------------------------------------------------------------------------
__global__ void agg_mlp_kernel(const float* __restrict__ vsrc,
                               const int*   __restrict__ nbr,
                               const float* __restrict__ W,     // [D, D] row-major
                               const float* __restrict__ bias,  // [D]
                               float*       __restrict__ out,   // [nrows, D]
                               int nrows)
{
    __shared__ float sW[DD * DD];      // 16 KB
    __shared__ float sB[DD];
    __shared__ float sAgg[8][DD];      // one 64-vec per warp

    const int tid = threadIdx.x;
    for (int i = tid; i < DD * DD; i += blockDim.x) sW[i] = W[i];
    if (tid < DD) sB[tid] = bias[tid];
    __syncthreads();

    const int warp = tid >> 5;
    const int lane = tid & 31;
    const int row  = blockIdx.x * 8 + warp;
    if (row >= nrows) return;

    // All 32 neighbor indices for this row, one per lane.
    const int myidx = __ldg(nbr + (size_t)row * KNBR + lane);

    float2 sum = make_float2(0.f, 0.f);
    #pragma unroll
    for (int k = 0; k < KNBR; ++k) {
        int idx = __shfl_sync(0xffffffffu, myidx, k);
        float2 v = __ldg((const float2*)(vsrc + (size_t)idx * DD) + lane);
        sum.x += v.x;
        sum.y += v.y;
    }
    const float inv = 1.0f / (float)KNBR;
    sAgg[warp][2 * lane]     = sum.x * inv;
    sAgg[warp][2 * lane + 1] = sum.y * inv;
    __syncwarp();

    // Matvec: lane computes output columns (lane) and (lane+32).
    float acc0 = sB[lane];
    float acc1 = sB[lane + 32];
    #pragma unroll
    for (int d = 0; d < DD; ++d) {
        float a = sAgg[warp][d];                 // broadcast read
        acc0 += a * sW[d * DD + lane];           // conflict-free
        acc1 += a * sW[d * DD + lane + 32];
    }
    acc0 = fmaxf(acc0, 0.f);
    acc1 = fmaxf(acc1, 0.f);
    out[(size_t)row * DD + lane]      = acc0;
    out[(size_t)row * DD + lane + 32] = acc1;
}

// ---------------------------------------------------------------------------
// Launch
// Inputs (metadata order): 0 feats, 1 W0, 2 b0, 3 W1, 4 b1,
//                          5 neigh_idx0, 6 neigh_idx1, 7 node_ids1 (UNUSED),
//                          8 node_ids2
// ---------------------------------------------------------------------------
extern "C" void kernel_launch(void* const* d_in, const int* in_sizes, int n_in,
                              void* d_out, int out_size)
{
    const float* feats      = (const float*)d_in[0];
    const float* W0         = (const float*)d_in[1];
    const float* b0         = (const float*)d_in[2];
    const float* W1         = (const float*)d_in[3];
    const float* b1         = (const float*)d_in[4];
    const int*   neigh_idx0 = (const int*)  d_in[5];
    const int*   neigh_idx1 = (const int*)  d_in[6];
    const int*   node_ids2  = (const int*)  d_in[8];
    float*       out        = (float*)d_out;

    float* v2;  cudaGetSymbolAddress((void**)&v2, g_v2);
    float* h1;  cudaGetSymbolAddress((void**)&h1, g_h1);

    // A: v2 = feats[node_ids2]
    {
        const int total = N2V * (DD / 4);
        gather_v2_kernel<<<(total + 255) / 256, 256>>>(feats, node_ids2);
    }
    // B: h1 = relu(mean(v2[neigh_idx1]) @ W0 + b0)
    agg_mlp_kernel<<<(N1V + 7) / 8, 256>>>(v2, neigh_idx1, W0, b0, h1, N1V);
    // C: out = relu(mean(h1[neigh_idx0]) @ W1 + b1)
    agg_mlp_kernel<<<(N0V + 7) / 8, 256>>>(h1, neigh_idx0, W1, b1, out, N0V);
}

// round 2
// speedup vs baseline: 1.1012x; 1.1012x over previous
#include <cuda_runtime.h>
#include <cuda_fp16.h>

// GraphSAGE 2-layer inference, fused. fp16-compressed hop-2 features.
#define N0V   8192
#define N1V   100000
#define N2V   300000
#define KNBR  32
#define DD    64

// Scratch (device globals — no allocation allowed in kernel_launch).
__device__ __half g_v2h[(size_t)N2V * DD];   // 38.4 MB  (L2-resident)
__device__ float  g_h1[(size_t)N1V * DD];    // 25.6 MB

// ---------------------------------------------------------------------------
// Kernel A: v2h = half(feats[node_ids2]).  Read 16B/thread, write 8B/thread.
// ---------------------------------------------------------------------------
__global__ void gather_v2h_kernel(const float* __restrict__ feats,
                                  const int*   __restrict__ node_ids2)
{
    int t = blockIdx.x * blockDim.x + threadIdx.x;
    const int total = N2V * (DD / 4);          // float4 granularity
    if (t >= total) return;
    int row = t >> 4;                          // 16 float4 per row
    int c   = t & 15;
    int src = __ldg(node_ids2 + row);
    float4 v = __ldg((const float4*)(feats + (size_t)src * DD) + c);
    __half2 h0 = __floats2half2_rn(v.x, v.y);
    __half2 h1 = __floats2half2_rn(v.z, v.w);
    uint2 packed;
    packed.x = *(unsigned int*)&h0;
    packed.y = *(unsigned int*)&h1;
    ((uint2*)(g_v2h + (size_t)row * DD))[c] = packed;
}

// ---------------------------------------------------------------------------
// Kernel B: per row — mean over KNBR fp16 neighbor rows (fp32 accum),
// then x@W0 + b0, ReLU, fp32 out. One warp per row; W in shared.
// Each lane loads one half2 (dims 2*lane, 2*lane+1) per neighbor row:
// 128B coalesced per row, 32 independent loads in flight per warp.
// ---------------------------------------------------------------------------
__global__ void agg_mlp_h_kernel(const __half* __restrict__ vsrc,
                                 const int*    __restrict__ nbr,
                                 const float*  __restrict__ W,     // [D, D]
                                 const float*  __restrict__ bias,  // [D]
                                 float*        __restrict__ out,   // [nrows, D]
                                 int nrows)
{
    __shared__ float sW[DD * DD];      // 16 KB
    __shared__ float sB[DD];
    __shared__ float sAgg[8][DD];

    const int tid = threadIdx.x;
    for (int i = tid; i < DD * DD; i += blockDim.x) sW[i] = W[i];
    if (tid < DD) sB[tid] = bias[tid];
    __syncthreads();

    const int warp = tid >> 5;
    const int lane = tid & 31;
    const int row  = blockIdx.x * 8 + warp;
    if (row >= nrows) return;

    const int myidx = __ldg(nbr + (size_t)row * KNBR + lane);

    float2 sum = make_float2(0.f, 0.f);
    #pragma unroll
    for (int k = 0; k < KNBR; ++k) {
        int idx = __shfl_sync(0xffffffffu, myidx, k);
        __half2 v = __ldg((const __half2*)(vsrc + (size_t)idx * DD) + lane);
        float2 f = __half22float2(v);
        sum.x += f.x;
        sum.y += f.y;
    }
    const float inv = 1.0f / (float)KNBR;
    sAgg[warp][2 * lane]     = sum.x * inv;
    sAgg[warp][2 * lane + 1] = sum.y * inv;
    __syncwarp();

    float acc0 = sB[lane];
    float acc1 = sB[lane + 32];
    #pragma unroll
    for (int d = 0; d < DD; ++d) {
        float a = sAgg[warp][d];
        acc0 += a * sW[d * DD + lane];
        acc1 += a * sW[d * DD + lane + 32];
    }
    out[(size_t)row * DD + lane]      = fmaxf(acc0, 0.f);
    out[(size_t)row * DD + lane + 32] = fmaxf(acc1, 0.f);
}

// ---------------------------------------------------------------------------
// Kernel C: same but fp32 input (h1), fp32 out (seed layer).
// ---------------------------------------------------------------------------
__global__ void agg_mlp_f_kernel(const float* __restrict__ vsrc,
                                 const int*   __restrict__ nbr,
                                 const float* __restrict__ W,
                                 const float* __restrict__ bias,
                                 float*       __restrict__ out,
                                 int nrows)
{
    __shared__ float sW[DD * DD];
    __shared__ float sB[DD];
    __shared__ float sAgg[8][DD];

    const int tid = threadIdx.x;
    for (int i = tid; i < DD * DD; i += blockDim.x) sW[i] = W[i];
    if (tid < DD) sB[tid] = bias[tid];
    __syncthreads();

    const int warp = tid >> 5;
    const int lane = tid & 31;
    const int row  = blockIdx.x * 8 + warp;
    if (row >= nrows) return;

    const int myidx = __ldg(nbr + (size_t)row * KNBR + lane);

    float2 sum = make_float2(0.f, 0.f);
    #pragma unroll
    for (int k = 0; k < KNBR; ++k) {
        int idx = __shfl_sync(0xffffffffu, myidx, k);
        float2 v = __ldg((const float2*)(vsrc + (size_t)idx * DD) + lane);
        sum.x += v.x;
        sum.y += v.y;
    }
    const float inv = 1.0f / (float)KNBR;
    sAgg[warp][2 * lane]     = sum.x * inv;
    sAgg[warp][2 * lane + 1] = sum.y * inv;
    __syncwarp();

    float acc0 = sB[lane];
    float acc1 = sB[lane + 32];
    #pragma unroll
    for (int d = 0; d < DD; ++d) {
        float a = sAgg[warp][d];
        acc0 += a * sW[d * DD + lane];
        acc1 += a * sW[d * DD + lane + 32];
    }
    out[(size_t)row * DD + lane]      = fmaxf(acc0, 0.f);
    out[(size_t)row * DD + lane + 32] = fmaxf(acc1, 0.f);
}

// ---------------------------------------------------------------------------
// Inputs: 0 feats, 1 W0, 2 b0, 3 W1, 4 b1, 5 neigh_idx0, 6 neigh_idx1,
//         7 node_ids1 (unused), 8 node_ids2
// ---------------------------------------------------------------------------
extern "C" void kernel_launch(void* const* d_in, const int* in_sizes, int n_in,
                              void* d_out, int out_size)
{
    const float* feats      = (const float*)d_in[0];
    const float* W0         = (const float*)d_in[1];
    const float* b0         = (const float*)d_in[2];
    const float* W1         = (const float*)d_in[3];
    const float* b1         = (const float*)d_in[4];
    const int*   neigh_idx0 = (const int*)  d_in[5];
    const int*   neigh_idx1 = (const int*)  d_in[6];
    const int*   node_ids2  = (const int*)  d_in[8];
    float*       out        = (float*)d_out;

    __half* v2h; cudaGetSymbolAddress((void**)&v2h, g_v2h);
    float*  h1;  cudaGetSymbolAddress((void**)&h1,  g_h1);

    {
        const int total = N2V * (DD / 4);
        gather_v2h_kernel<<<(total + 255) / 256, 256>>>(feats, node_ids2);
    }
    agg_mlp_h_kernel<<<(N1V + 7) / 8, 256>>>(v2h, neigh_idx1, W0, b0, h1, N1V);
    agg_mlp_f_kernel<<<(N0V + 7) / 8, 256>>>(h1, neigh_idx0, W1, b1, out, N0V);
}

// round 3
// speedup vs baseline: 1.2688x; 1.1522x over previous
#include <cuda_runtime.h>
#include <cuda_fp16.h>

#define N0V   8192
#define N1V   100000
#define N2V   300000
#define KNBR  32
#define DD    64

// Scratch (device globals — allocation in kernel_launch is forbidden).
__device__ __half g_v2h[(size_t)N2V * DD];   // 38.4 MB (L2-resident gather target)
__device__ __half g_h1h[(size_t)N1V * DD];   // 12.8 MB

// ---------------------------------------------------------------------------
// Kernel A: v2h = half(feats[node_ids2]).  2 rows per thread for MLP.
// ---------------------------------------------------------------------------
__global__ void gather_v2h_kernel(const float* __restrict__ feats,
                                  const int*   __restrict__ node_ids2)
{
    int t = blockIdx.x * blockDim.x + threadIdx.x;
    const int half_total = (N2V / 2) * (DD / 4);
    if (t >= half_total) return;
    int row  = t >> 4;                 // 16 float4 per row
    int c    = t & 15;
    int row2 = row + N2V / 2;
    int s1 = __ldg(node_ids2 + row);
    int s2 = __ldg(node_ids2 + row2);
    float4 v1 = __ldg((const float4*)(feats + (size_t)s1 * DD) + c);
    float4 v2 = __ldg((const float4*)(feats + (size_t)s2 * DD) + c);

    __half2 a0 = __floats2half2_rn(v1.x, v1.y);
    __half2 a1 = __floats2half2_rn(v1.z, v1.w);
    __half2 b0 = __floats2half2_rn(v2.x, v2.y);
    __half2 b1 = __floats2half2_rn(v2.z, v2.w);
    uint2 p1, p2;
    p1.x = *(unsigned int*)&a0;  p1.y = *(unsigned int*)&a1;
    p2.x = *(unsigned int*)&b0;  p2.y = *(unsigned int*)&b1;
    ((uint2*)g_v2h)[(size_t)row  * 16 + c] = p1;
    ((uint2*)g_v2h)[(size_t)row2 * 16 + c] = p2;
}

// ---------------------------------------------------------------------------
// Kernel B/C: one warp per row. Gather-mean over KNBR fp16 rows (fp32 accum),
// then x@W + b + ReLU with W held in REGISTERS (lane owns cols 2l, 2l+1) and
// a-values broadcast by shuffle. Zero shared memory -> no crossbar bottleneck.
// ---------------------------------------------------------------------------
template<bool HALF_OUT>
__global__ void __launch_bounds__(128) agg_mlp_reg_kernel(
    const __half2* __restrict__ vsrc,   // [nsrc][DD/2]
    const int*     __restrict__ nbr,    // [nrows][KNBR]
    const float*   __restrict__ W,      // [DD][DD] row-major
    const float*   __restrict__ bias,   // [DD]
    void*          __restrict__ outp,   // [nrows][DD] half or float
    int nrows)
{
    const int lane = threadIdx.x & 31;
    const int warp = threadIdx.x >> 5;
    const int row  = blockIdx.x * 4 + warp;
    if (row >= nrows) return;

    // Start the index load early (long latency).
    const int myidx = __ldg(nbr + (size_t)row * KNBR + lane);

    // W columns (2*lane, 2*lane+1): 64 coalesced float2 loads, stays in regs.
    float wx[DD], wy[DD];
    #pragma unroll
    for (int d = 0; d < DD; ++d) {
        float2 wv = __ldg((const float2*)W + d * 32 + lane);
        wx[d] = wv.x;  wy[d] = wv.y;
    }
    const float2 bv = __ldg((const float2*)bias + lane);

    // Gather-mean: 32 independent 128B row loads, lane reads dims 2l, 2l+1.
    float sx = 0.f, sy = 0.f;
    #pragma unroll
    for (int k = 0; k < KNBR; ++k) {
        int idx = __shfl_sync(0xffffffffu, myidx, k);
        __half2 hv = __ldg(vsrc + (size_t)idx * (DD / 2) + lane);
        float2 f = __half22float2(hv);
        sx += f.x;  sy += f.y;
    }
    sx *= (1.0f / KNBR);
    sy *= (1.0f / KNBR);

    // Matvec: a_d broadcast via shuffle; 4 accumulator chains.
    float acc0 = bv.x, acc1 = bv.y, acc2 = 0.f, acc3 = 0.f;
    #pragma unroll
    for (int k = 0; k < 32; k += 2) {
        {
            float ax = __shfl_sync(0xffffffffu, sx, k);
            float ay = __shfl_sync(0xffffffffu, sy, k);
            acc0 = fmaf(ax, wx[2 * k],     acc0);
            acc1 = fmaf(ax, wy[2 * k],     acc1);
            acc0 = fmaf(ay, wx[2 * k + 1], acc0);
            acc1 = fmaf(ay, wy[2 * k + 1], acc1);
        }
        {
            int k1 = k + 1;
            float ax = __shfl_sync(0xffffffffu, sx, k1);
            float ay = __shfl_sync(0xffffffffu, sy, k1);
            acc2 = fmaf(ax, wx[2 * k1],     acc2);
            acc3 = fmaf(ax, wy[2 * k1],     acc3);
            acc2 = fmaf(ay, wx[2 * k1 + 1], acc2);
            acc3 = fmaf(ay, wy[2 * k1 + 1], acc3);
        }
    }
    float o0 = fmaxf(acc0 + acc2, 0.f);
    float o1 = fmaxf(acc1 + acc3, 0.f);

    if (HALF_OUT) {
        ((__half2*)outp)[(size_t)row * 32 + lane] = __floats2half2_rn(o0, o1);
    } else {
        ((float2*)outp)[(size_t)row * 32 + lane] = make_float2(o0, o1);
    }
}

// ---------------------------------------------------------------------------
// Inputs: 0 feats, 1 W0, 2 b0, 3 W1, 4 b1, 5 neigh_idx0, 6 neigh_idx1,
//         7 node_ids1 (unused), 8 node_ids2
// ---------------------------------------------------------------------------
extern "C" void kernel_launch(void* const* d_in, const int* in_sizes, int n_in,
                              void* d_out, int out_size)
{
    const float* feats      = (const float*)d_in[0];
    const float* W0         = (const float*)d_in[1];
    const float* b0         = (const float*)d_in[2];
    const float* W1         = (const float*)d_in[3];
    const float* b1         = (const float*)d_in[4];
    const int*   neigh_idx0 = (const int*)  d_in[5];
    const int*   neigh_idx1 = (const int*)  d_in[6];
    const int*   node_ids2  = (const int*)  d_in[8];
    float*       out        = (float*)d_out;

    __half* v2h; cudaGetSymbolAddress((void**)&v2h, g_v2h);
    __half* h1h; cudaGetSymbolAddress((void**)&h1h, g_h1h);

    {
        const int half_total = (N2V / 2) * (DD / 4);
        gather_v2h_kernel<<<(half_total + 255) / 256, 256>>>(feats, node_ids2);
    }
    agg_mlp_reg_kernel<true ><<<(N1V + 3) / 4, 128>>>(
        (const __half2*)v2h, neigh_idx1, W0, b0, (void*)h1h, N1V);
    agg_mlp_reg_kernel<false><<<(N0V + 3) / 4, 128>>>(
        (const __half2*)h1h, neigh_idx0, W1, b1, (void*)out, N0V);
}